// round 9
// baseline (speedup 1.0000x reference)
#include <cuda_runtime.h>
#include <cstdint>

#define BB 64
#define TT 4096
#define CC 51
#define DD 64
#define NTHREADS 128
#define LN_EPS 1e-5f

typedef unsigned long long ull;

// Packed fp32x2 ops (Blackwell; PTX-only)
#define FMA2(d, a, b, c) \
    asm("fma.rn.f32x2 %0, %1, %2, %3;" : "=l"(d) : "l"(a), "l"(b), "l"(c))
#define ADD2(d, a, b) \
    asm("add.rn.f32x2 %0, %1, %2;" : "=l"(d) : "l"(a), "l"(b))
#define MUL2(d, a, b) \
    asm("mul.rn.f32x2 %0, %1, %2;" : "=l"(d) : "l"(a), "l"(b))

static __device__ __forceinline__ float lo32(ull v) { return __uint_as_float((unsigned)v); }
static __device__ __forceinline__ float hi32(ull v) { return __uint_as_float((unsigned)(v >> 32)); }
static __device__ __forceinline__ ull pack2(float x, float y) {
    return (ull)__float_as_uint(x) | ((ull)__float_as_uint(y) << 32);
}
static __device__ __forceinline__ ull dup2(float x) { return pack2(x, x); }

// ---------------------------------------------------------------------------
// Globals written by precompute kernel
// ---------------------------------------------------------------------------
__device__ int    g_mask_dtype;        // 1=int32 {0,1}, 2=float32 {0,1.0f}, 0=uint8
__device__ float  g_bias[BB * DD];     // per batch: sum of Wm over sensor-masked c
__device__ float2 g_cvec[BB * 32];     // per batch, lane: LN(sum_all Wm) const row

static __device__ __forceinline__ int mask_val(const void* p, long i, int dt)
{
    if (dt == 1) return ((const int*)p)[i] != 0;
    if (dt == 2) return ((const float*)p)[i] != 0.0f;
    return ((const unsigned char*)p)[i] != 0;
}

// ---------------------------------------------------------------------------
// Per-batch precompute (grid=64, block=32). Self-detects mask dtype from the
// first 1024 words of time_mask (Bernoulli(0.3): classification unambiguous).
// ---------------------------------------------------------------------------
extern "C" __global__ void precompute_batch_kernel(const float* __restrict__ Wm,
                                                   const void* __restrict__ smask,
                                                   const float* __restrict__ gamma,
                                                   const float* __restrict__ beta,
                                                   const unsigned* __restrict__ tmw)
{
    const int b = blockIdx.x, lane = threadIdx.x;

    int ok_i = 1, ok_f = 1;
#pragma unroll
    for (int k = 0; k < 32; ++k) {
        unsigned w = tmw[lane + 32 * k];
        if (w > 1u)                      ok_i = 0;
        if (w != 0u && w != 0x3f800000u) ok_f = 0;
    }
    ok_i = __all_sync(0xffffffffu, ok_i);
    ok_f = __all_sync(0xffffffffu, ok_f);
    const int dt = ok_i ? 1 : (ok_f ? 2 : 0);
    if (b == 0 && lane == 0) g_mask_dtype = dt;

    float2 ws = make_float2(0.f, 0.f), bs = make_float2(0.f, 0.f);
#pragma unroll
    for (int c = 0; c < CC; ++c) {
        float2 wm = *(const float2*)(Wm + c * DD + 2 * lane);
        ws.x += wm.x; ws.y += wm.y;
        if (mask_val(smask, (long)b * CC + c, dt)) { bs.x += wm.x; bs.y += wm.y; }
    }
    float2 g2 = *(const float2*)(gamma + 2 * lane);
    float2 b2 = *(const float2*)(beta  + 2 * lane);
    float s = ws.x + ws.y, q = ws.x * ws.x + ws.y * ws.y;
#pragma unroll
    for (int o = 16; o > 0; o >>= 1) {
        s += __shfl_xor_sync(0xffffffffu, s, o);
        q += __shfl_xor_sync(0xffffffffu, q, o);
    }
    float mu = s * (1.f / 64.f);
    float r  = rsqrtf(fmaf(-mu, mu, q * (1.f / 64.f)) + LN_EPS);
    float2 cv;
    cv.x = fmaf((ws.x - mu) * r, g2.x, b2.x);
    cv.y = fmaf((ws.y - mu) * r, g2.y, b2.y);
    g_bias[b * DD + 2 * lane]     = bs.x;
    g_bias[b * DD + 2 * lane + 1] = bs.y;
    g_cvec[b * 32 + lane]         = cv;
}

// ---------------------------------------------------------------------------
// Main kernel SMEM layout (bytes):
//   [0)      float xs_t[51][132]   transposed, token-compacted x   = 26928
//   [26928)  ull   Wd[51][64]      duplicated (w,w) pairs          = 26112
//   [53040)  int   tokmap[128]     slot -> token index in tile
//   [53552)  int   slotmap[128]    token -> slot (-1 if masked)
//   [54064)  int   wcnt[4]
//   [54080)  uchar sm_sh[64]
// ---------------------------------------------------------------------------
#define XT_STRIDE 132
#define SM_XT   0
#define SM_WD   26928
#define SM_TOK  53040
#define SM_SLOT 53552
#define SM_WCNT 54064
#define SM_SMSH 54080
#define SM_TOTAL 54144

extern "C" __global__ void __launch_bounds__(NTHREADS, 4)
fused_proj_ln_kernel(const float* __restrict__ x,
                     const float* __restrict__ W,
                     const float* __restrict__ gamma,
                     const float* __restrict__ beta,
                     const void* __restrict__ time_mask,
                     const void* __restrict__ sensor_mask,
                     float* __restrict__ out)
{
    extern __shared__ char smem[];
    float*         xs_t    = (float*)(smem + SM_XT);
    ull*           Wd      = (ull*)(smem + SM_WD);
    int*           tokmap  = (int*)(smem + SM_TOK);
    int*           slotmap = (int*)(smem + SM_SLOT);
    int*           wcnt    = (int*)(smem + SM_WCNT);
    unsigned char* sm_sh   = (unsigned char*)(smem + SM_SMSH);

    const int tid  = threadIdx.x;
    const int lane = tid & 31;
    const int wid  = tid >> 5;

    const int  b    = blockIdx.x >> 5;           // 32 tiles per batch
    const int  tb   = (blockIdx.x & 31) * 128;
    const long tok0 = (long)b * TT + tb;
    const int  dt   = g_mask_dtype;

    // ---- stage sensor mask; init tokmap ----
    if (tid < CC) sm_sh[tid] = (unsigned char)mask_val(sensor_mask, (long)b * CC + tid, dt);
    tokmap[tid] = 0;

    // ---- time mask + warp counts ----
    const int un  = !mask_val(time_mask, tok0 + tid, dt);   // this thread's token
    unsigned  um  = __ballot_sync(0xffffffffu, un);
    if (lane == 0) wcnt[wid] = __popc(um);
    __syncthreads();                                        // sync #1

    // ---- block compaction: slot assignment ----
    int woff = 0;
#pragma unroll
    for (int w = 0; w < 4; ++w) woff += (w < wid) ? wcnt[w] : 0;
    const int nslots  = wcnt[0] + wcnt[1] + wcnt[2] + wcnt[3];
    const int ngroups = (nslots + 15) >> 4;
    const int myslot  = woff + __popc(um & ((1u << lane) - 1u));
    slotmap[tid] = un ? myslot : -1;
    if (un) tokmap[myslot] = tid;
    __syncthreads();                                        // sync #2

    // ---- stage Wd: duplicated (w,w) pairs, masked columns zeroed ----
    for (int i = tid; i < CC * 16; i += NTHREADS) {         // 816 float4 of W
        float4 w4 = ((const float4*)W)[i];
        int c = i >> 4;
        if (sm_sh[c]) w4 = make_float4(0.f, 0.f, 0.f, 0.f);
        ull* dst = Wd + c * 64 + (i & 15) * 4;
        ulonglong2 t0; t0.x = dup2(w4.x); t0.y = dup2(w4.y);
        ulonglong2 t1; t1.x = dup2(w4.z); t1.y = dup2(w4.w);
        *(ulonglong2*)(dst)     = t0;
        *(ulonglong2*)(dst + 2) = t1;
    }

    // ---- stage x: coalesced reads, transposed + compacted scatter ----
    {
        const float* xg = x + tok0 * CC;
        int i = tid;
        int tok = (tid >= 102) ? 2 : (tid >= 51 ? 1 : 0);
        int c   = tid - 51 * tok;
#pragma unroll 4
        for (int k = 0; k < CC; ++k) {                      // 51*128 == 128*51
            float v = xg[i];
            int s = slotmap[tok];
            if (s >= 0) xs_t[c * XT_STRIDE + s] = v;
            i += NTHREADS;
            c += 26; tok += 2;
            if (c >= CC) { c -= CC; ++tok; }
        }
    }

    // ---- per-lane constants ----
    const float2 bb   = *(const float2*)(g_bias + b * DD + 2 * lane);
    const ull    bll0 = dup2(bb.x), bll1 = dup2(bb.y);
    const float2 cvec = g_cvec[b * 32 + lane];
    const float2 g2   = *(const float2*)(gamma + 2 * lane);
    const float2 b2   = *(const float2*)(beta  + 2 * lane);
    const ull    gd0  = dup2(g2.x), gd1 = dup2(g2.y);
    const ull    bd0  = dup2(b2.x), bd1 = dup2(b2.y);

    float2* out2 = (float2*)out;

    // ---- time-masked tokens: predicated constant-row stores (warp's 32 tokens)
    {
        unsigned mm = ~um;
        float2* ob = out2 + (tok0 + wid * 32) * 32 + lane;
#pragma unroll
        for (int r = 0; r < 32; ++r)
            if ((mm >> r) & 1u) ob[r * 32] = cvec;
    }
    __syncthreads();                                        // sync #3

    // ---- compute: groups of 16 compacted slots (8 token-pairs) per warp ----
    for (int g = wid; g < ngroups; g += 4) {
        const int base = g * 16;

        ull a00 = bll0, a01 = bll1, a10 = bll0, a11 = bll1;
        ull a20 = bll0, a21 = bll1, a30 = bll0, a31 = bll1;
        ull a40 = bll0, a41 = bll1, a50 = bll0, a51 = bll1;
        ull a60 = bll0, a61 = bll1, a70 = bll0, a71 = bll1;

        const char* xp = (const char*)(xs_t + base);
        const ulonglong2* wp = (const ulonglong2*)Wd + lane;

#pragma unroll 3
        for (int c = 0; c < CC; ++c) {
            ulonglong2 w = wp[c * 32];                       // (w2l,w2l),(w2l+1,w2l+1)
            const ulonglong2* xr = (const ulonglong2*)(xp + c * (XT_STRIDE * 4));
            ulonglong2 xA = xr[0];                           // slots 0..3 (pairs 0,1)
            ulonglong2 xB = xr[1];                           // pairs 2,3
            ulonglong2 xC = xr[2];                           // pairs 4,5
            ulonglong2 xD = xr[3];                           // pairs 6,7

            FMA2(a00, xA.x, w.x, a00); FMA2(a01, xA.x, w.y, a01);
            FMA2(a10, xA.y, w.x, a10); FMA2(a11, xA.y, w.y, a11);
            FMA2(a20, xB.x, w.x, a20); FMA2(a21, xB.x, w.y, a21);
            FMA2(a30, xB.y, w.x, a30); FMA2(a31, xB.y, w.y, a31);
            FMA2(a40, xC.x, w.x, a40); FMA2(a41, xC.x, w.y, a41);
            FMA2(a50, xC.y, w.x, a50); FMA2(a51, xC.y, w.y, a51);
            FMA2(a60, xD.x, w.x, a60); FMA2(a61, xD.x, w.y, a61);
            FMA2(a70, xD.y, w.x, a70); FMA2(a71, xD.y, w.y, a71);
        }

        // ---- LN for 8 token-pairs: packed (t_even, t_odd) reductions ----
        ull A0[8] = {a00, a10, a20, a30, a40, a50, a60, a70};
        ull A1[8] = {a01, a11, a21, a31, a41, a51, a61, a71};
        ull s[8], q[8];
#pragma unroll
        for (int p = 0; p < 8; ++p) {
            ADD2(s[p], A0[p], A1[p]);
            MUL2(q[p], A0[p], A0[p]);
            FMA2(q[p], A1[p], A1[p], q[p]);
        }
#pragma unroll
        for (int o = 16; o > 0; o >>= 1) {
#pragma unroll
            for (int p = 0; p < 8; ++p) {
                ull ts = __shfl_xor_sync(0xffffffffu, s[p], o);
                ull tq = __shfl_xor_sync(0xffffffffu, q[p], o);
                ADD2(s[p], s[p], ts);
                ADD2(q[p], q[p], tq);
            }
        }
#pragma unroll
        for (int p = 0; p < 8; ++p) {
            float s0 = lo32(s[p]), s1 = hi32(s[p]);
            float q0 = lo32(q[p]), q1 = hi32(q[p]);
            float mu0 = s0 * (1.f / 64.f), mu1 = s1 * (1.f / 64.f);
            float r0  = rsqrtf(fmaf(-mu0, mu0, q0 * (1.f / 64.f)) + LN_EPS);
            float r1  = rsqrtf(fmaf(-mu1, mu1, q1 * (1.f / 64.f)) + LN_EPS);
            ull rp = pack2(r0, r1);
            ull nm = pack2(-mu0, -mu1);
            ull n0, n1, t;
            ADD2(t, A0[p], nm); MUL2(t, t, rp); FMA2(n0, t, gd0, bd0);
            ADD2(t, A1[p], nm); MUL2(t, t, rp); FMA2(n1, t, gd1, bd1);

            int sl = base + 2 * p;
            int t0 = tokmap[sl];
            int t1 = tokmap[sl + 1 < 128 ? sl + 1 : 127];
            if (sl < nslots)
                out2[(tok0 + t0) * 32 + lane] = make_float2(lo32(n0), lo32(n1));
            if (sl + 1 < nslots)
                out2[(tok0 + t1) * 32 + lane] = make_float2(hi32(n0), hi32(n1));
        }
    }
}

extern "C" void kernel_launch(void* const* d_in, const int* in_sizes, int n_in,
                              void* d_out, int out_size)
{
    const float* x     = (const float*)d_in[0];
    const float* W     = (const float*)d_in[1];
    const float* Wm    = (const float*)d_in[2];
    const float* gamma = (const float*)d_in[3];
    const float* beta  = (const float*)d_in[4];
    const void*  tmask = d_in[5];
    const void*  smask = d_in[6];

    (void)in_sizes; (void)n_in; (void)out_size;

    cudaFuncSetAttribute(fused_proj_ln_kernel,
                         cudaFuncAttributeMaxDynamicSharedMemorySize, SM_TOTAL);

    precompute_batch_kernel<<<BB, 32>>>(Wm, smask, gamma, beta,
                                        (const unsigned*)tmask);

    const int nblocks = BB * (TT / 128);   // 2048
    fused_proj_ln_kernel<<<nblocks, NTHREADS, SM_TOTAL>>>(
        x, W, gamma, beta, tmask, smask, (float*)d_out);
}

// round 10
// speedup vs baseline: 1.0186x; 1.0186x over previous
#include <cuda_runtime.h>
#include <cstdint>

#define BB 64
#define TT 4096
#define CC 51
#define DD 64
#define NTHREADS 128
#define LN_EPS 1e-5f

typedef unsigned long long ull;

// Packed fp32x2 ops (Blackwell; PTX-only)
#define FMA2(d, a, b, c) \
    asm("fma.rn.f32x2 %0, %1, %2, %3;" : "=l"(d) : "l"(a), "l"(b), "l"(c))
#define ADD2(d, a, b) \
    asm("add.rn.f32x2 %0, %1, %2;" : "=l"(d) : "l"(a), "l"(b))
#define MUL2(d, a, b) \
    asm("mul.rn.f32x2 %0, %1, %2;" : "=l"(d) : "l"(a), "l"(b))

static __device__ __forceinline__ float lo32(ull v) { return __uint_as_float((unsigned)v); }
static __device__ __forceinline__ float hi32(ull v) { return __uint_as_float((unsigned)(v >> 32)); }
static __device__ __forceinline__ ull pack2(float x, float y) {
    return (ull)__float_as_uint(x) | ((ull)__float_as_uint(y) << 32);
}
static __device__ __forceinline__ ull dup2(float x) { return pack2(x, x); }

// ---------------------------------------------------------------------------
// Globals written by precompute kernel
// ---------------------------------------------------------------------------
__device__ int    g_mask_dtype;        // 1=int32 {0,1}, 2=float32 {0,1.0f}, 0=uint8
__device__ float  g_bias[BB * DD];     // per batch: sum of Wm over sensor-masked c
__device__ float2 g_cvec[BB * 32];     // per batch, lane: LN(sum_all Wm) const row

static __device__ __forceinline__ int mask_val(const void* p, long i, int dt)
{
    if (dt == 1) return ((const int*)p)[i] != 0;
    if (dt == 2) return ((const float*)p)[i] != 0.0f;
    return ((const unsigned char*)p)[i] != 0;
}

// ---------------------------------------------------------------------------
// Per-batch precompute (grid=64, block=32). Self-detects mask dtype from the
// first 1024 words of time_mask (Bernoulli(0.3): classification unambiguous).
// ---------------------------------------------------------------------------
extern "C" __global__ void precompute_batch_kernel(const float* __restrict__ Wm,
                                                   const void* __restrict__ smask,
                                                   const float* __restrict__ gamma,
                                                   const float* __restrict__ beta,
                                                   const unsigned* __restrict__ tmw)
{
    const int b = blockIdx.x, lane = threadIdx.x;

    int ok_i = 1, ok_f = 1;
#pragma unroll
    for (int k = 0; k < 32; ++k) {
        unsigned w = tmw[lane + 32 * k];
        if (w > 1u)                      ok_i = 0;
        if (w != 0u && w != 0x3f800000u) ok_f = 0;
    }
    ok_i = __all_sync(0xffffffffu, ok_i);
    ok_f = __all_sync(0xffffffffu, ok_f);
    const int dt = ok_i ? 1 : (ok_f ? 2 : 0);
    if (b == 0 && lane == 0) g_mask_dtype = dt;

    float2 ws = make_float2(0.f, 0.f), bs = make_float2(0.f, 0.f);
#pragma unroll
    for (int c = 0; c < CC; ++c) {
        float2 wm = *(const float2*)(Wm + c * DD + 2 * lane);
        ws.x += wm.x; ws.y += wm.y;
        if (mask_val(smask, (long)b * CC + c, dt)) { bs.x += wm.x; bs.y += wm.y; }
    }
    float2 g2 = *(const float2*)(gamma + 2 * lane);
    float2 b2 = *(const float2*)(beta  + 2 * lane);
    float s = ws.x + ws.y, q = ws.x * ws.x + ws.y * ws.y;
#pragma unroll
    for (int o = 16; o > 0; o >>= 1) {
        s += __shfl_xor_sync(0xffffffffu, s, o);
        q += __shfl_xor_sync(0xffffffffu, q, o);
    }
    float mu = s * (1.f / 64.f);
    float r  = rsqrtf(fmaf(-mu, mu, q * (1.f / 64.f)) + LN_EPS);
    float2 cv;
    cv.x = fmaf((ws.x - mu) * r, g2.x, b2.x);
    cv.y = fmaf((ws.y - mu) * r, g2.y, b2.y);
    g_bias[b * DD + 2 * lane]     = bs.x;
    g_bias[b * DD + 2 * lane + 1] = bs.y;
    g_cvec[b * 32 + lane]         = cv;
}

// ---------------------------------------------------------------------------
// Main kernel SMEM layout (bytes):
//   [0)      float xs_t[51][132]   transposed, token-compacted x   = 26928
//   [26928)  ull   Wd[51][64]      duplicated (w,w) pairs          = 26112
//   [53040)  int   tokmap[128]     slot -> token index in tile
//   [53552)  int   slotmap[128]    token -> slot (-1 if masked)
//   [54064)  int   wcnt[4]
//   [54080)  uchar sm_sh[64]
// ---------------------------------------------------------------------------
#define XT_STRIDE 132
#define SM_XT   0
#define SM_WD   26928
#define SM_TOK  53040
#define SM_SLOT 53552
#define SM_WCNT 54064
#define SM_SMSH 54080
#define SM_TOTAL 54144

extern "C" __global__ void __launch_bounds__(NTHREADS, 4)
fused_proj_ln_kernel(const float* __restrict__ x,
                     const float* __restrict__ W,
                     const float* __restrict__ gamma,
                     const float* __restrict__ beta,
                     const void* __restrict__ time_mask,
                     const void* __restrict__ sensor_mask,
                     float* __restrict__ out)
{
    extern __shared__ char smem[];
    float*         xs_t    = (float*)(smem + SM_XT);
    ull*           Wd      = (ull*)(smem + SM_WD);
    int*           tokmap  = (int*)(smem + SM_TOK);
    int*           slotmap = (int*)(smem + SM_SLOT);
    int*           wcnt    = (int*)(smem + SM_WCNT);
    unsigned char* sm_sh   = (unsigned char*)(smem + SM_SMSH);

    const int tid  = threadIdx.x;
    const int lane = tid & 31;
    const int wid  = tid >> 5;

    const int  b    = blockIdx.x >> 5;           // 32 tiles per batch
    const int  tb   = (blockIdx.x & 31) * 128;
    const long tok0 = (long)b * TT + tb;
    const int  dt   = g_mask_dtype;

    // ---- stage sensor mask; init tokmap ----
    if (tid < CC) sm_sh[tid] = (unsigned char)mask_val(sensor_mask, (long)b * CC + tid, dt);
    tokmap[tid] = 0;

    // ---- time mask + warp counts ----
    const int un  = !mask_val(time_mask, tok0 + tid, dt);   // this thread's token
    unsigned  um  = __ballot_sync(0xffffffffu, un);
    if (lane == 0) wcnt[wid] = __popc(um);
    __syncthreads();                                        // sync #1

    // ---- block compaction: slot assignment ----
    int woff = 0;
#pragma unroll
    for (int w = 0; w < 4; ++w) woff += (w < wid) ? wcnt[w] : 0;
    const int nslots  = wcnt[0] + wcnt[1] + wcnt[2] + wcnt[3];
    const int ngroups = (nslots + 15) >> 4;
    const int myslot  = woff + __popc(um & ((1u << lane) - 1u));
    slotmap[tid] = un ? myslot : -1;
    if (un) tokmap[myslot] = tid;
    __syncthreads();                                        // sync #2

    // ---- stage Wd: duplicated (w,w) pairs, masked columns zeroed ----
    for (int i = tid; i < CC * 16; i += NTHREADS) {         // 816 float4 of W
        float4 w4 = ((const float4*)W)[i];
        int c = i >> 4;
        if (sm_sh[c]) w4 = make_float4(0.f, 0.f, 0.f, 0.f);
        ull* dst = Wd + c * 64 + (i & 15) * 4;
        ulonglong2 t0; t0.x = dup2(w4.x); t0.y = dup2(w4.y);
        ulonglong2 t1; t1.x = dup2(w4.z); t1.y = dup2(w4.w);
        *(ulonglong2*)(dst)     = t0;
        *(ulonglong2*)(dst + 2) = t1;
    }

    // ---- stage x: coalesced reads, transposed + compacted scatter ----
    {
        const float* xg = x + tok0 * CC;
        int i = tid;
        int tok = (tid >= 102) ? 2 : (tid >= 51 ? 1 : 0);
        int c   = tid - 51 * tok;
#pragma unroll 4
        for (int k = 0; k < CC; ++k) {                      // 51*128 == 128*51
            float v = xg[i];
            int s = slotmap[tok];
            if (s >= 0) xs_t[c * XT_STRIDE + s] = v;
            i += NTHREADS;
            c += 26; tok += 2;
            if (c >= CC) { c -= CC; ++tok; }
        }
    }

    // ---- per-lane constants ----
    const float2 bb   = *(const float2*)(g_bias + b * DD + 2 * lane);
    const ull    bll0 = dup2(bb.x), bll1 = dup2(bb.y);
    const float2 cvec = g_cvec[b * 32 + lane];
    const float2 g2   = *(const float2*)(gamma + 2 * lane);
    const float2 b2   = *(const float2*)(beta  + 2 * lane);
    const ull    gd0  = dup2(g2.x), gd1 = dup2(g2.y);
    const ull    bd0  = dup2(b2.x), bd1 = dup2(b2.y);

    float2* out2 = (float2*)out;

    // ---- time-masked tokens: predicated constant-row stores (warp's 32 tokens)
    {
        unsigned mm = ~um;
        float2* ob = out2 + (tok0 + wid * 32) * 32 + lane;
#pragma unroll
        for (int r = 0; r < 32; ++r)
            if ((mm >> r) & 1u) ob[r * 32] = cvec;
    }
    __syncthreads();                                        // sync #3

    // ---- compute: groups of 16 compacted slots (8 token-pairs) per warp ----
    for (int g = wid; g < ngroups; g += 4) {
        const int base = g * 16;

        ull a00 = bll0, a01 = bll1, a10 = bll0, a11 = bll1;
        ull a20 = bll0, a21 = bll1, a30 = bll0, a31 = bll1;
        ull a40 = bll0, a41 = bll1, a50 = bll0, a51 = bll1;
        ull a60 = bll0, a61 = bll1, a70 = bll0, a71 = bll1;

        const char* xp = (const char*)(xs_t + base);
        const ulonglong2* wp = (const ulonglong2*)Wd + lane;

#pragma unroll 3
        for (int c = 0; c < CC; ++c) {
            ulonglong2 w = wp[c * 32];                       // (w2l,w2l),(w2l+1,w2l+1)
            const ulonglong2* xr = (const ulonglong2*)(xp + c * (XT_STRIDE * 4));
            ulonglong2 xA = xr[0];                           // slots 0..3 (pairs 0,1)
            ulonglong2 xB = xr[1];                           // pairs 2,3
            ulonglong2 xC = xr[2];                           // pairs 4,5
            ulonglong2 xD = xr[3];                           // pairs 6,7

            FMA2(a00, xA.x, w.x, a00); FMA2(a01, xA.x, w.y, a01);
            FMA2(a10, xA.y, w.x, a10); FMA2(a11, xA.y, w.y, a11);
            FMA2(a20, xB.x, w.x, a20); FMA2(a21, xB.x, w.y, a21);
            FMA2(a30, xB.y, w.x, a30); FMA2(a31, xB.y, w.y, a31);
            FMA2(a40, xC.x, w.x, a40); FMA2(a41, xC.x, w.y, a41);
            FMA2(a50, xC.y, w.x, a50); FMA2(a51, xC.y, w.y, a51);
            FMA2(a60, xD.x, w.x, a60); FMA2(a61, xD.x, w.y, a61);
            FMA2(a70, xD.y, w.x, a70); FMA2(a71, xD.y, w.y, a71);
        }

        // ---- LN for 8 token-pairs: packed (t_even, t_odd) reductions ----
        ull A0[8] = {a00, a10, a20, a30, a40, a50, a60, a70};
        ull A1[8] = {a01, a11, a21, a31, a41, a51, a61, a71};
        ull s[8], q[8];
#pragma unroll
        for (int p = 0; p < 8; ++p) {
            ADD2(s[p], A0[p], A1[p]);
            MUL2(q[p], A0[p], A0[p]);
            FMA2(q[p], A1[p], A1[p], q[p]);
        }
#pragma unroll
        for (int o = 16; o > 0; o >>= 1) {
#pragma unroll
            for (int p = 0; p < 8; ++p) {
                ull ts = __shfl_xor_sync(0xffffffffu, s[p], o);
                ull tq = __shfl_xor_sync(0xffffffffu, q[p], o);
                ADD2(s[p], s[p], ts);
                ADD2(q[p], q[p], tq);
            }
        }
#pragma unroll
        for (int p = 0; p < 8; ++p) {
            float s0 = lo32(s[p]), s1 = hi32(s[p]);
            float q0 = lo32(q[p]), q1 = hi32(q[p]);
            float mu0 = s0 * (1.f / 64.f), mu1 = s1 * (1.f / 64.f);
            float r0  = rsqrtf(fmaf(-mu0, mu0, q0 * (1.f / 64.f)) + LN_EPS);
            float r1  = rsqrtf(fmaf(-mu1, mu1, q1 * (1.f / 64.f)) + LN_EPS);
            ull rp = pack2(r0, r1);
            ull nm = pack2(-mu0, -mu1);
            ull n0, n1, t;
            ADD2(t, A0[p], nm); MUL2(t, t, rp); FMA2(n0, t, gd0, bd0);
            ADD2(t, A1[p], nm); MUL2(t, t, rp); FMA2(n1, t, gd1, bd1);

            int sl = base + 2 * p;
            int t0 = tokmap[sl];
            int t1 = tokmap[sl + 1 < 128 ? sl + 1 : 127];
            if (sl < nslots)
                out2[(tok0 + t0) * 32 + lane] = make_float2(lo32(n0), lo32(n1));
            if (sl + 1 < nslots)
                out2[(tok0 + t1) * 32 + lane] = make_float2(hi32(n0), hi32(n1));
        }
    }
}

extern "C" void kernel_launch(void* const* d_in, const int* in_sizes, int n_in,
                              void* d_out, int out_size)
{
    const float* x     = (const float*)d_in[0];
    const float* W     = (const float*)d_in[1];
    const float* Wm    = (const float*)d_in[2];
    const float* gamma = (const float*)d_in[3];
    const float* beta  = (const float*)d_in[4];
    const void*  tmask = d_in[5];
    const void*  smask = d_in[6];

    (void)in_sizes; (void)n_in; (void)out_size;

    cudaFuncSetAttribute(fused_proj_ln_kernel,
                         cudaFuncAttributeMaxDynamicSharedMemorySize, SM_TOTAL);

    precompute_batch_kernel<<<BB, 32>>>(Wm, smask, gamma, beta,
                                        (const unsigned*)tmask);

    const int nblocks = BB * (TT / 128);   // 2048
    fused_proj_ln_kernel<<<nblocks, NTHREADS, SM_TOTAL>>>(
        x, W, gamma, beta, tmask, smask, (float*)d_out);
}